// round 1
// baseline (speedup 1.0000x reference)
#include <cuda_runtime.h>
#include <cuda_fp16.h>
#include <cstdint>

#define M_DIM 4096
#define K_DIM 4096
#define N_DIM 11008
#define GROUPK 128
#define N_GROUPS (K_DIM / GROUPK)   // 32

#define BM 128
#define BN 128
#define BK 32
#define PAD 8
#define THREADS 256

// Scratch (device globals are the sanctioned scratch mechanism — no runtime alloc)
__device__ __half Xh[(size_t)M_DIM * K_DIM];   // 32 MB
__device__ __half Wh[(size_t)N_DIM * K_DIM];   // 90 MB

// ---------------------------------------------------------------------------
// fp32 -> fp16 conversion of activations
// ---------------------------------------------------------------------------
__global__ void convert_x_kernel(const float* __restrict__ x) {
    size_t i = (size_t)blockIdx.x * blockDim.x + threadIdx.x;
    size_t n4 = (size_t)M_DIM * K_DIM / 4;
    if (i >= n4) return;
    float4 v = reinterpret_cast<const float4*>(x)[i];
    union { uint2 u; __half2 h[2]; } pk;
    pk.h[0] = __floats2half2_rn(v.x, v.y);
    pk.h[1] = __floats2half2_rn(v.z, v.w);
    reinterpret_cast<uint2*>(Xh)[i] = pk.u;
}

// ---------------------------------------------------------------------------
// RTN dequant: W = (q - 8) * scale[o][k/128], int32 codes -> fp16
// ---------------------------------------------------------------------------
__global__ void dequant_w_kernel(const int* __restrict__ qw,
                                 const float* __restrict__ scales) {
    size_t i = (size_t)blockIdx.x * blockDim.x + threadIdx.x;  // 4 elems each
    size_t n4 = (size_t)N_DIM * K_DIM / 4;
    if (i >= n4) return;
    int4 q = reinterpret_cast<const int4*>(qw)[i];
    size_t e = i * 4;
    int o = (int)(e / K_DIM);
    int k = (int)(e % K_DIM);
    int g = k / GROUPK;                  // 4 consecutive k never cross a group
    float s = scales[(size_t)o * N_GROUPS + g];
    union { uint2 u; __half2 h[2]; } pk;
    pk.h[0] = __floats2half2_rn((float)(q.x - 8) * s, (float)(q.y - 8) * s);
    pk.h[1] = __floats2half2_rn((float)(q.z - 8) * s, (float)(q.w - 8) * s);
    reinterpret_cast<uint2*>(Wh)[i] = pk.u;
}

// ---------------------------------------------------------------------------
// fp16 GEMM: C[M,N] = Xh[M,K] * Wh[N,K]^T, fp32 accumulate
// mma.sync.m16n8k16, cp.async double-buffered, GROUP_M block swizzle
// ---------------------------------------------------------------------------
__global__ void __launch_bounds__(THREADS, 1) gemm_kernel(float* __restrict__ C) {
    __shared__ __half As[2][BM][BK + PAD];
    __shared__ __half Bs[2][BN][BK + PAD];

    const int tid = threadIdx.x;
    const int lane = tid & 31;
    const int warp = tid >> 5;
    const int wm = warp >> 2;        // 0..1  (warp row)
    const int wn = warp & 3;         // 0..3  (warp col)
    const int groupID = lane >> 2;   // 0..7
    const int tg = lane & 3;         // 0..3

    // ---- L2-friendly block swizzle (triton GROUP_M scheme) ----
    const int num_pid_m = M_DIM / BM;   // 32
    const int num_pid_n = N_DIM / BN;   // 86
    const int GROUP_M = 8;
    int pid = blockIdx.x;
    int group_size = GROUP_M * num_pid_n;
    int group_id = pid / group_size;
    int first_pid_m = group_id * GROUP_M;
    int group_m = num_pid_m - first_pid_m;
    if (group_m > GROUP_M) group_m = GROUP_M;
    int pid_m = first_pid_m + (pid % group_m);
    int pid_n = (pid % group_size) / group_m;

    const int blockM = pid_m * BM;
    const int blockN = pid_n * BN;

    const __half* Ag = Xh + (size_t)blockM * K_DIM;
    const __half* Bg = Wh + (size_t)blockN * K_DIM;

    float acc[4][4][4];
    #pragma unroll
    for (int i = 0; i < 4; i++)
        #pragma unroll
        for (int j = 0; j < 4; j++)
            #pragma unroll
            for (int r = 0; r < 4; r++) acc[i][j][r] = 0.0f;

    // ---- async tile loader: 128 rows x 32 halves (64B) per tile ----
    auto load_stage = [&](int kt, int buf) {
        int k0 = kt * BK;
        #pragma unroll
        for (int t = 0; t < 2; ++t) {
            int chunk = tid + t * THREADS;     // 0..511
            int row = chunk >> 2;              // 0..127
            int c16 = chunk & 3;               // 16B chunk within row
            const __half* gA = Ag + (size_t)row * K_DIM + k0 + c16 * 8;
            uint32_t sA = (uint32_t)__cvta_generic_to_shared(&As[buf][row][c16 * 8]);
            asm volatile("cp.async.cg.shared.global [%0], [%1], 16;\n"
                         :: "r"(sA), "l"(gA));
            const __half* gB = Bg + (size_t)row * K_DIM + k0 + c16 * 8;
            uint32_t sB = (uint32_t)__cvta_generic_to_shared(&Bs[buf][row][c16 * 8]);
            asm volatile("cp.async.cg.shared.global [%0], [%1], 16;\n"
                         :: "r"(sB), "l"(gB));
        }
        asm volatile("cp.async.commit_group;\n");
    };

    const int KT = K_DIM / BK;   // 128
    load_stage(0, 0);

    for (int kt = 0; kt < KT; ++kt) {
        int buf = kt & 1;
        asm volatile("cp.async.wait_group 0;\n");
        __syncthreads();
        if (kt + 1 < KT) load_stage(kt + 1, buf ^ 1);

        #pragma unroll
        for (int ks = 0; ks < 2; ++ks) {
            const int k0 = ks * 16;
            uint32_t afrag[4][4];
            #pragma unroll
            for (int i = 0; i < 4; i++) {
                int mrow = wm * 64 + i * 16 + groupID;
                afrag[i][0] = *(const uint32_t*)&As[buf][mrow][k0 + tg * 2];
                afrag[i][1] = *(const uint32_t*)&As[buf][mrow + 8][k0 + tg * 2];
                afrag[i][2] = *(const uint32_t*)&As[buf][mrow][k0 + tg * 2 + 8];
                afrag[i][3] = *(const uint32_t*)&As[buf][mrow + 8][k0 + tg * 2 + 8];
            }
            uint32_t bfrag[4][2];
            #pragma unroll
            for (int j = 0; j < 4; j++) {
                int nrow = wn * 32 + j * 8 + groupID;
                bfrag[j][0] = *(const uint32_t*)&Bs[buf][nrow][k0 + tg * 2];
                bfrag[j][1] = *(const uint32_t*)&Bs[buf][nrow][k0 + tg * 2 + 8];
            }
            #pragma unroll
            for (int i = 0; i < 4; i++) {
                #pragma unroll
                for (int j = 0; j < 4; j++) {
                    asm volatile(
                        "mma.sync.aligned.m16n8k16.row.col.f32.f16.f16.f32 "
                        "{%0,%1,%2,%3}, {%4,%5,%6,%7}, {%8,%9}, {%0,%1,%2,%3};\n"
                        : "+f"(acc[i][j][0]), "+f"(acc[i][j][1]),
                          "+f"(acc[i][j][2]), "+f"(acc[i][j][3])
                        : "r"(afrag[i][0]), "r"(afrag[i][1]),
                          "r"(afrag[i][2]), "r"(afrag[i][3]),
                          "r"(bfrag[j][0]), "r"(bfrag[j][1]));
                }
            }
        }
    }

    // ---- epilogue: fp32 stores (paired as float2) ----
    #pragma unroll
    for (int i = 0; i < 4; i++) {
        int r0 = blockM + wm * 64 + i * 16 + groupID;
        #pragma unroll
        for (int j = 0; j < 4; j++) {
            int cx = blockN + wn * 32 + j * 8 + tg * 2;
            *reinterpret_cast<float2*>(&C[(size_t)r0 * N_DIM + cx]) =
                make_float2(acc[i][j][0], acc[i][j][1]);
            *reinterpret_cast<float2*>(&C[(size_t)(r0 + 8) * N_DIM + cx]) =
                make_float2(acc[i][j][2], acc[i][j][3]);
        }
    }
}

// ---------------------------------------------------------------------------
extern "C" void kernel_launch(void* const* d_in, const int* in_sizes, int n_in,
                              void* d_out, int out_size) {
    const float* x  = (const float*)d_in[0];
    const int*   qw = (const int*)d_in[1];
    const float* sc = (const float*)d_in[2];
    float* out = (float*)d_out;

    {
        size_t n4 = (size_t)M_DIM * K_DIM / 4;
        convert_x_kernel<<<(unsigned)((n4 + 255) / 256), 256>>>(x);
    }
    {
        size_t n4 = (size_t)N_DIM * K_DIM / 4;
        dequant_w_kernel<<<(unsigned)((n4 + 255) / 256), 256>>>(qw, sc);
    }
    gemm_kernel<<<(M_DIM / BM) * (N_DIM / BN), THREADS>>>(out);
}

// round 3
// speedup vs baseline: 1.6865x; 1.6865x over previous
#include <cuda_runtime.h>
#include <cuda_fp16.h>
#include <cstdint>

#define M_DIM 4096
#define K_DIM 4096
#define N_DIM 11008
#define N_GROUPS 32

#define BM 128
#define BN 128
#define BK 64
#define NSTAGE 4
#define KT_TOTAL (K_DIM / BK)    // 64
#define NTILE_M (M_DIM / BM)     // 32
#define NTILE_N (N_DIM / BN)     // 86

#define A_STG_BYTES (BM * 128)   // 16384: 128 rows x (64 fp16 = 128B), SW128
#define B_STG_BYTES (BN * 128)   // 16384
#define STAGE_BYTES (A_STG_BYTES + B_STG_BYTES)

#define SOFF_FULL 0
#define SOFF_A    1024
#define SOFF_B    (SOFF_A + NSTAGE * A_STG_BYTES)
#define SMEM_TOTAL (SOFF_B + NSTAGE * B_STG_BYTES)   // 132096

// Tiled + SW128-pre-swizzled fp16 operands (device globals = sanctioned scratch)
__device__ __half Xs[(size_t)M_DIM * K_DIM];   // 32 MB: [m_tile][k_stage] 16KB blocks
__device__ __half Ws[(size_t)N_DIM * K_DIM];   // 90 MB: [n_tile][k_stage] 16KB blocks

// ---------------------------------------------------------------------------
#define MBAR_INIT(a, c) \
    asm volatile("mbarrier.init.shared.b64 [%0], %1;" :: "r"(a), "r"(c) : "memory")
#define MBAR_EXPECT_TX(a, b) \
    asm volatile("mbarrier.arrive.expect_tx.shared.b64 _, [%0], %1;" :: "r"(a), "r"(b) : "memory")
#define BULK_G2S(dst, src, bytes, mbar) \
    asm volatile("cp.async.bulk.shared::cta.global.mbarrier::complete_tx::bytes [%0], [%1], %2, [%3];" \
                 :: "r"(dst), "l"(src), "r"(bytes), "r"(mbar) : "memory")

#define MBAR_WAIT_PARITY(addr, parity) do {                                      \
    uint32_t _m = (addr); uint32_t _p = (parity); uint32_t _d;                   \
    asm volatile("{\n\t.reg .pred p;\n\t"                                        \
        "mbarrier.try_wait.parity.acquire.cta.shared::cta.b64 p, [%1], %2;\n\t"  \
        "selp.b32 %0, 1, 0, p;\n\t}"                                             \
        : "=r"(_d) : "r"(_m), "r"(_p) : "memory");                               \
    if (!_d) {                                                                   \
        asm volatile("{\n\t.reg .pred P1;\n\t"                                   \
            "WL_%=:\n\t"                                                         \
            "mbarrier.try_wait.parity.acquire.cta.shared::cta.b64 P1, [%0], %1, 0x989680;\n\t" \
            "@P1 bra.uni WD_%=;\n\t"                                             \
            "bra.uni WL_%=;\n\t"                                                 \
            "WD_%=:\n\t}"                                                        \
            :: "r"(_m), "r"(_p) : "memory");                                     \
    }                                                                            \
} while (0)

#define LDMATRIX_X4(r0, r1, r2, r3, a) \
    asm volatile("ldmatrix.sync.aligned.m8n8.x4.shared.b16 {%0,%1,%2,%3}, [%4];" \
                 : "=r"(r0), "=r"(r1), "=r"(r2), "=r"(r3) : "r"(a))

// ---------------------------------------------------------------------------
// fp32 -> fp16, tiled + SW128-swizzled (MMA-ready 16KB blocks)
// ---------------------------------------------------------------------------
__global__ void convert_x_kernel(const float* __restrict__ x) {
    size_t i = (size_t)blockIdx.x * blockDim.x + threadIdx.x;   // 8 halves/thread
    size_t m = i >> 9;
    int k = (int)(i & 511) * 8;
    const float4* src = reinterpret_cast<const float4*>(x + m * K_DIM + k);
    float4 v0 = src[0], v1 = src[1];
    union { uint4 u; __half2 h[4]; } o;
    o.h[0] = __floats2half2_rn(v0.x, v0.y);
    o.h[1] = __floats2half2_rn(v0.z, v0.w);
    o.h[2] = __floats2half2_rn(v1.x, v1.y);
    o.h[3] = __floats2half2_rn(v1.z, v1.w);
    int mt = (int)(m >> 7), r = (int)(m & 127);
    int stage = k >> 6, c = k & 63;
    uint32_t off = (uint32_t)(r * 128 + c * 2);
    uint32_t sw = off ^ ((off >> 3) & 0x70);
    char* dst = (char*)Xs + (((size_t)mt * KT_TOTAL + stage) << 14) + sw;
    *reinterpret_cast<uint4*>(dst) = o.u;
}

// ---------------------------------------------------------------------------
// RTN dequant -> fp16, tiled + SW128-swizzled (16KB blocks, BN=128)
// ---------------------------------------------------------------------------
__global__ void dequant_w_kernel(const int* __restrict__ qw,
                                 const float* __restrict__ scales) {
    size_t i = (size_t)blockIdx.x * blockDim.x + threadIdx.x;   // 8 elems/thread
    size_t n = i >> 9;
    int k = (int)(i & 511) * 8;
    const int4* src = reinterpret_cast<const int4*>(qw + n * K_DIM + k);
    int4 q0 = src[0], q1 = src[1];
    float s = scales[n * N_GROUPS + (k >> 7)];
    union { uint4 u; __half2 h[4]; } o;
    o.h[0] = __floats2half2_rn((float)(q0.x - 8) * s, (float)(q0.y - 8) * s);
    o.h[1] = __floats2half2_rn((float)(q0.z - 8) * s, (float)(q0.w - 8) * s);
    o.h[2] = __floats2half2_rn((float)(q1.x - 8) * s, (float)(q1.y - 8) * s);
    o.h[3] = __floats2half2_rn((float)(q1.z - 8) * s, (float)(q1.w - 8) * s);
    int nt = (int)(n >> 7), r = (int)(n & 127);
    int stage = k >> 6, c = k & 63;
    uint32_t off = (uint32_t)(r * 128 + c * 2);
    uint32_t sw = off ^ ((off >> 3) & 0x70);
    char* dst = (char*)Ws + (((size_t)nt * KT_TOTAL + stage) << 14) + sw;
    *reinterpret_cast<uint4*>(dst) = o.u;
}

// ---------------------------------------------------------------------------
// HMMA GEMM: C = Xs * Ws^T, 128x128 tile, 4-stage bulk-copy ring, ldmatrix feed
// ---------------------------------------------------------------------------
__global__ void __launch_bounds__(256, 1) gemm_hmma(float* __restrict__ C) {
    extern __shared__ char smem[];
    uint32_t sb = (uint32_t)__cvta_generic_to_shared(smem);
    const int tid = threadIdx.x;
    const int lane = tid & 31;
    const int warp = tid >> 5;
    const int wm = warp >> 2;        // 0..1
    const int wn = warp & 3;         // 0..3

    const int pid = blockIdx.x;
    const int pid_n = pid / NTILE_M;     // column-major order: A tiles hot in L2
    const int pid_m = pid % NTILE_M;

    if (tid == 0) {
        #pragma unroll
        for (int s = 0; s < NSTAGE; ++s) MBAR_INIT(sb + SOFF_FULL + s * 8, 1);
    }
    __syncthreads();

    const char* Ab = (const char*)Xs + ((size_t)pid_m * KT_TOTAL << 14);
    const char* Bb = (const char*)Ws + ((size_t)pid_n * KT_TOTAL << 14);

    if (tid == 0) {
        #pragma unroll
        for (int s = 0; s < NSTAGE - 1; ++s) {
            uint32_t fb = sb + SOFF_FULL + s * 8;
            MBAR_EXPECT_TX(fb, (uint32_t)STAGE_BYTES);
            BULK_G2S(sb + SOFF_A + s * A_STG_BYTES, Ab + ((size_t)s << 14),
                     (uint32_t)A_STG_BYTES, fb);
            BULK_G2S(sb + SOFF_B + s * B_STG_BYTES, Bb + ((size_t)s << 14),
                     (uint32_t)B_STG_BYTES, fb);
        }
    }

    float acc[4][4][4];
    #pragma unroll
    for (int i = 0; i < 4; i++)
        #pragma unroll
        for (int j = 0; j < 4; j++)
            #pragma unroll
            for (int r = 0; r < 4; r++) acc[i][j][r] = 0.0f;

    // per-thread ldmatrix row assignment (m8n8.x4: lanes 0-7 -> mat0 rows, etc.)
    const int lrow = (lane & 7) + ((lane >> 3) & 1) * 8;  // row within 16-block
    const int ksel = (lane >> 4);                         // 0: k0-7, 1: k8-15
    int rA[4], rB[2];
    #pragma unroll
    for (int i = 0; i < 4; i++) rA[i] = wm * 64 + i * 16 + lrow;
    #pragma unroll
    for (int j = 0; j < 2; j++) rB[j] = wn * 32 + j * 16 + lrow;

    for (int kt = 0; kt < KT_TOTAL; ++kt) {
        const int s = kt & (NSTAGE - 1);
        MBAR_WAIT_PARITY(sb + SOFF_FULL + s * 8, (uint32_t)((kt >> 2) & 1));

        if (tid == 0 && kt + NSTAGE - 1 < KT_TOTAL) {
            int kn = kt + NSTAGE - 1;
            int s2 = kn & (NSTAGE - 1);
            uint32_t fb = sb + SOFF_FULL + s2 * 8;
            MBAR_EXPECT_TX(fb, (uint32_t)STAGE_BYTES);
            BULK_G2S(sb + SOFF_A + s2 * A_STG_BYTES, Ab + ((size_t)kn << 14),
                     (uint32_t)A_STG_BYTES, fb);
            BULK_G2S(sb + SOFF_B + s2 * B_STG_BYTES, Bb + ((size_t)kn << 14),
                     (uint32_t)B_STG_BYTES, fb);
        }

        const uint32_t Abase = sb + SOFF_A + s * A_STG_BYTES;
        const uint32_t Bbase = sb + SOFF_B + s * B_STG_BYTES;

        #pragma unroll
        for (int kc = 0; kc < BK / 16; ++kc) {
            const int kseg = kc * 2 + ksel;   // 16B segment index (0..7)
            uint32_t a[4][4];
            #pragma unroll
            for (int i = 0; i < 4; i++) {
                uint32_t ad = Abase + rA[i] * 128 + ((kseg ^ (rA[i] & 7)) << 4);
                LDMATRIX_X4(a[i][0], a[i][1], a[i][2], a[i][3], ad);
            }
            uint32_t b[2][4];
            #pragma unroll
            for (int j = 0; j < 2; j++) {
                uint32_t bd = Bbase + rB[j] * 128 + ((kseg ^ (rB[j] & 7)) << 4);
                LDMATRIX_X4(b[j][0], b[j][1], b[j][2], b[j][3], bd);
            }
            #pragma unroll
            for (int i = 0; i < 4; i++) {
                #pragma unroll
                for (int j = 0; j < 4; j++) {
                    const int jj = j >> 1, lo = j & 1;
                    asm volatile(
                        "mma.sync.aligned.m16n8k16.row.col.f32.f16.f16.f32 "
                        "{%0,%1,%2,%3}, {%4,%5,%6,%7}, {%8,%9}, {%0,%1,%2,%3};\n"
                        : "+f"(acc[i][j][0]), "+f"(acc[i][j][1]),
                          "+f"(acc[i][j][2]), "+f"(acc[i][j][3])
                        : "r"(a[i][0]), "r"(a[i][1]), "r"(a[i][2]), "r"(a[i][3]),
                          "r"(b[jj][lo]), "r"(b[jj][2 + lo]));
                }
            }
        }
        __syncthreads();
    }

    // epilogue
    #pragma unroll
    for (int i = 0; i < 4; i++) {
        int r0 = pid_m * BM + wm * 64 + i * 16 + (lane >> 2);
        #pragma unroll
        for (int j = 0; j < 4; j++) {
            int cx = pid_n * BN + wn * 32 + j * 8 + (lane & 3) * 2;
            *reinterpret_cast<float2*>(&C[(size_t)r0 * N_DIM + cx]) =
                make_float2(acc[i][j][0], acc[i][j][1]);
            *reinterpret_cast<float2*>(&C[(size_t)(r0 + 8) * N_DIM + cx]) =
                make_float2(acc[i][j][2], acc[i][j][3]);
        }
    }
}

// ---------------------------------------------------------------------------
extern "C" void kernel_launch(void* const* d_in, const int* in_sizes, int n_in,
                              void* d_out, int out_size) {
    const float* x  = (const float*)d_in[0];
    const int*   qw = (const int*)d_in[1];
    const float* sc = (const float*)d_in[2];
    float* out = (float*)d_out;

    convert_x_kernel<<<(M_DIM * (K_DIM / 8)) / 256, 256>>>(x);
    dequant_w_kernel<<<(N_DIM * (K_DIM / 8)) / 256, 256>>>(qw, sc);

    cudaFuncSetAttribute(gemm_hmma, cudaFuncAttributeMaxDynamicSharedMemorySize, SMEM_TOTAL);
    gemm_hmma<<<NTILE_M * NTILE_N, 256, SMEM_TOTAL>>>(out);
}

// round 4
// speedup vs baseline: 1.9604x; 1.1624x over previous
#include <cuda_runtime.h>
#include <cuda_fp16.h>
#include <cstdint>

#define M_DIM 4096
#define K_DIM 4096
#define N_DIM 11008
#define N_GROUPS 32

#define BM 128
#define BN 128
#define BK 64
#define NSTAGE 3
#define KT_TOTAL (K_DIM / BK)    // 64
#define NTILE_M (M_DIM / BM)     // 32
#define NTILE_N (N_DIM / BN)     // 86

#define A_STG_BYTES (BM * 128)   // 16384: 128 rows x (64 fp16 = 128B), SW128
#define B_STG_BYTES (BN * 128)   // 16384
#define STAGE_BYTES (A_STG_BYTES + B_STG_BYTES)

#define SOFF_FULL  0
#define SOFF_EMPTY 64
#define SOFF_A     1024
#define SOFF_B     (SOFF_A + NSTAGE * A_STG_BYTES)       // 50176
#define SMEM_TOTAL (SOFF_B + NSTAGE * B_STG_BYTES)       // 99328 -> 2 CTAs/SM

#define NTHREADS 288   // 8 compute warps + 1 producer warp

// Tiled + SW128-pre-swizzled fp16 operands (device globals = sanctioned scratch)
__device__ __half Xs[(size_t)M_DIM * K_DIM];   // 32 MB: [m_tile][k_stage] 16KB blocks
__device__ __half Ws[(size_t)N_DIM * K_DIM];   // 90 MB: [n_tile][k_stage] 16KB blocks

// ---------------------------------------------------------------------------
#define MBAR_INIT(a, c) \
    asm volatile("mbarrier.init.shared.b64 [%0], %1;" :: "r"(a), "r"(c) : "memory")
#define MBAR_EXPECT_TX(a, b) \
    asm volatile("mbarrier.arrive.expect_tx.shared.b64 _, [%0], %1;" :: "r"(a), "r"(b) : "memory")
#define MBAR_ARRIVE(a) \
    asm volatile("mbarrier.arrive.shared.b64 _, [%0];" :: "r"(a) : "memory")
#define BULK_G2S(dst, src, bytes, mbar) \
    asm volatile("cp.async.bulk.shared::cta.global.mbarrier::complete_tx::bytes [%0], [%1], %2, [%3];" \
                 :: "r"(dst), "l"(src), "r"(bytes), "r"(mbar) : "memory")

#define MBAR_WAIT_PARITY(addr, parity) do {                                      \
    uint32_t _m = (addr); uint32_t _p = (parity); uint32_t _d;                   \
    asm volatile("{\n\t.reg .pred p;\n\t"                                        \
        "mbarrier.try_wait.parity.acquire.cta.shared::cta.b64 p, [%1], %2;\n\t"  \
        "selp.b32 %0, 1, 0, p;\n\t}"                                             \
        : "=r"(_d) : "r"(_m), "r"(_p) : "memory");                               \
    if (!_d) {                                                                   \
        asm volatile("{\n\t.reg .pred P1;\n\t"                                   \
            "WL_%=:\n\t"                                                         \
            "mbarrier.try_wait.parity.acquire.cta.shared::cta.b64 P1, [%0], %1, 0x989680;\n\t" \
            "@P1 bra.uni WD_%=;\n\t"                                             \
            "bra.uni WL_%=;\n\t"                                                 \
            "WD_%=:\n\t}"                                                        \
            :: "r"(_m), "r"(_p) : "memory");                                     \
    }                                                                            \
} while (0)

#define LDMATRIX_X4(r0, r1, r2, r3, a) \
    asm volatile("ldmatrix.sync.aligned.m8n8.x4.shared.b16 {%0,%1,%2,%3}, [%4];" \
                 : "=r"(r0), "=r"(r1), "=r"(r2), "=r"(r3) : "r"(a))

// ---------------------------------------------------------------------------
// fp32 -> fp16, tiled + SW128-swizzled (MMA-ready 16KB blocks)
// ---------------------------------------------------------------------------
__global__ void convert_x_kernel(const float* __restrict__ x) {
    size_t i = (size_t)blockIdx.x * blockDim.x + threadIdx.x;   // 8 halves/thread
    size_t m = i >> 9;
    int k = (int)(i & 511) * 8;
    const float4* src = reinterpret_cast<const float4*>(x + m * K_DIM + k);
    float4 v0 = src[0], v1 = src[1];
    union { uint4 u; __half2 h[4]; } o;
    o.h[0] = __floats2half2_rn(v0.x, v0.y);
    o.h[1] = __floats2half2_rn(v0.z, v0.w);
    o.h[2] = __floats2half2_rn(v1.x, v1.y);
    o.h[3] = __floats2half2_rn(v1.z, v1.w);
    int mt = (int)(m >> 7), r = (int)(m & 127);
    int stage = k >> 6, c = k & 63;
    uint32_t off = (uint32_t)(r * 128 + c * 2);
    uint32_t sw = off ^ ((off >> 3) & 0x70);
    char* dst = (char*)Xs + (((size_t)mt * KT_TOTAL + stage) << 14) + sw;
    *reinterpret_cast<uint4*>(dst) = o.u;
}

// ---------------------------------------------------------------------------
// RTN dequant -> fp16, tiled + SW128-swizzled (16KB blocks)
// ---------------------------------------------------------------------------
__global__ void dequant_w_kernel(const int* __restrict__ qw,
                                 const float* __restrict__ scales) {
    size_t i = (size_t)blockIdx.x * blockDim.x + threadIdx.x;   // 8 elems/thread
    size_t n = i >> 9;
    int k = (int)(i & 511) * 8;
    const int4* src = reinterpret_cast<const int4*>(qw + n * K_DIM + k);
    int4 q0 = src[0], q1 = src[1];
    float s = scales[n * N_GROUPS + (k >> 7)];
    union { uint4 u; __half2 h[4]; } o;
    o.h[0] = __floats2half2_rn((float)(q0.x - 8) * s, (float)(q0.y - 8) * s);
    o.h[1] = __floats2half2_rn((float)(q0.z - 8) * s, (float)(q0.w - 8) * s);
    o.h[2] = __floats2half2_rn((float)(q1.x - 8) * s, (float)(q1.y - 8) * s);
    o.h[3] = __floats2half2_rn((float)(q1.z - 8) * s, (float)(q1.w - 8) * s);
    int nt = (int)(n >> 7), r = (int)(n & 127);
    int stage = k >> 6, c = k & 63;
    uint32_t off = (uint32_t)(r * 128 + c * 2);
    uint32_t sw = off ^ ((off >> 3) & 0x70);
    char* dst = (char*)Ws + (((size_t)nt * KT_TOTAL + stage) << 14) + sw;
    *reinterpret_cast<uint4*>(dst) = o.u;
}

// ---------------------------------------------------------------------------
// HMMA GEMM: 128x128 tile, 3-stage bulk ring, producer warp, per-warp barriers
// ---------------------------------------------------------------------------
__global__ void __launch_bounds__(NTHREADS, 2) gemm_hmma(float* __restrict__ C) {
    extern __shared__ char smem[];
    uint32_t sb = (uint32_t)__cvta_generic_to_shared(smem);
    const int tid = threadIdx.x;
    const int lane = tid & 31;
    const int warp = tid >> 5;          // 0..7 compute, 8 producer

    const int pid = blockIdx.x;
    const int pid_n = pid / NTILE_M;    // column-major: A working set hot in L2
    const int pid_m = pid % NTILE_M;

    if (tid == 0) {
        #pragma unroll
        for (int s = 0; s < NSTAGE; ++s) {
            MBAR_INIT(sb + SOFF_FULL + s * 8, 1);
            MBAR_INIT(sb + SOFF_EMPTY + s * 8, 8);   // one arrive per compute warp
        }
    }
    __syncthreads();

    if (warp == 8) {
        // ---------------- producer warp ----------------
        if (lane == 0) {
            const char* Ab = (const char*)Xs + ((size_t)pid_m * KT_TOTAL << 14);
            const char* Bb = (const char*)Ws + ((size_t)pid_n * KT_TOTAL << 14);
            int s = 0, ph = 1;
            for (int kt = 0; kt < KT_TOTAL; ++kt) {
                MBAR_WAIT_PARITY(sb + SOFF_EMPTY + s * 8, (uint32_t)ph);
                uint32_t fb = sb + SOFF_FULL + s * 8;
                MBAR_EXPECT_TX(fb, (uint32_t)STAGE_BYTES);
                BULK_G2S(sb + SOFF_A + s * A_STG_BYTES, Ab + ((size_t)kt << 14),
                         (uint32_t)A_STG_BYTES, fb);
                BULK_G2S(sb + SOFF_B + s * B_STG_BYTES, Bb + ((size_t)kt << 14),
                         (uint32_t)B_STG_BYTES, fb);
                if (++s == NSTAGE) { s = 0; ph ^= 1; }
            }
        }
        return;
    }

    // ---------------- compute warps ----------------
    const int wm = warp >> 2;        // 0..1
    const int wn = warp & 3;         // 0..3

    float acc[4][4][4];
    #pragma unroll
    for (int i = 0; i < 4; i++)
        #pragma unroll
        for (int j = 0; j < 4; j++)
            #pragma unroll
            for (int r = 0; r < 4; r++) acc[i][j][r] = 0.0f;

    const int lrow = (lane & 7) + ((lane >> 3) & 1) * 8;
    const int ksel = (lane >> 4);
    int rA[4], rB[2];
    #pragma unroll
    for (int i = 0; i < 4; i++) rA[i] = wm * 64 + i * 16 + lrow;
    #pragma unroll
    for (int j = 0; j < 2; j++) rB[j] = wn * 32 + j * 16 + lrow;

    int s = 0, ph = 0;
    for (int kt = 0; kt < KT_TOTAL; ++kt) {
        MBAR_WAIT_PARITY(sb + SOFF_FULL + s * 8, (uint32_t)ph);

        const uint32_t Abase = sb + SOFF_A + s * A_STG_BYTES;
        const uint32_t Bbase = sb + SOFF_B + s * B_STG_BYTES;

        #pragma unroll
        for (int kc = 0; kc < BK / 16; ++kc) {
            const int kseg = kc * 2 + ksel;
            uint32_t a[4][4];
            #pragma unroll
            for (int i = 0; i < 4; i++) {
                uint32_t ad = Abase + rA[i] * 128 + ((kseg ^ (rA[i] & 7)) << 4);
                LDMATRIX_X4(a[i][0], a[i][1], a[i][2], a[i][3], ad);
            }
            uint32_t b[2][4];
            #pragma unroll
            for (int j = 0; j < 2; j++) {
                uint32_t bd = Bbase + rB[j] * 128 + ((kseg ^ (rB[j] & 7)) << 4);
                LDMATRIX_X4(b[j][0], b[j][1], b[j][2], b[j][3], bd);
            }
            #pragma unroll
            for (int i = 0; i < 4; i++) {
                #pragma unroll
                for (int j = 0; j < 4; j++) {
                    const int jj = j >> 1, lo = j & 1;
                    asm volatile(
                        "mma.sync.aligned.m16n8k16.row.col.f32.f16.f16.f32 "
                        "{%0,%1,%2,%3}, {%4,%5,%6,%7}, {%8,%9}, {%0,%1,%2,%3};\n"
                        : "+f"(acc[i][j][0]), "+f"(acc[i][j][1]),
                          "+f"(acc[i][j][2]), "+f"(acc[i][j][3])
                        : "r"(a[i][0]), "r"(a[i][1]), "r"(a[i][2]), "r"(a[i][3]),
                          "r"(b[jj][lo]), "r"(b[jj][2 + lo]));
                }
            }
        }

        __syncwarp();
        if (lane == 0) MBAR_ARRIVE(sb + SOFF_EMPTY + s * 8);
        if (++s == NSTAGE) { s = 0; ph ^= 1; }
    }

    // epilogue
    #pragma unroll
    for (int i = 0; i < 4; i++) {
        int r0 = pid_m * BM + wm * 64 + i * 16 + (lane >> 2);
        #pragma unroll
        for (int j = 0; j < 4; j++) {
            int cx = pid_n * BN + wn * 32 + j * 8 + (lane & 3) * 2;
            *reinterpret_cast<float2*>(&C[(size_t)r0 * N_DIM + cx]) =
                make_float2(acc[i][j][0], acc[i][j][1]);
            *reinterpret_cast<float2*>(&C[(size_t)(r0 + 8) * N_DIM + cx]) =
                make_float2(acc[i][j][2], acc[i][j][3]);
        }
    }
}

// ---------------------------------------------------------------------------
extern "C" void kernel_launch(void* const* d_in, const int* in_sizes, int n_in,
                              void* d_out, int out_size) {
    const float* x  = (const float*)d_in[0];
    const int*   qw = (const int*)d_in[1];
    const float* sc = (const float*)d_in[2];
    float* out = (float*)d_out;

    convert_x_kernel<<<(M_DIM * (K_DIM / 8)) / 256, 256>>>(x);
    dequant_w_kernel<<<(N_DIM * (K_DIM / 8)) / 256, 256>>>(qw, sc);

    cudaFuncSetAttribute(gemm_hmma, cudaFuncAttributeMaxDynamicSharedMemorySize, SMEM_TOTAL);
    gemm_hmma<<<NTILE_M * NTILE_N, NTHREADS, SMEM_TOTAL>>>(out);
}